// round 16
// baseline (speedup 1.0000x reference)
#include <cuda_runtime.h>

#define Wd   1024
#define Hd   1024
#define RPB  8
#define NBLK 2048                 // single strip per block
#define TPB  256                  // 256 threads * 4 floats = 1024 = one row

// 1 / (16 * 1024 * 1024) = 2^-24, exact power of two -> exact scaling
#define INV_N 5.9604644775390625e-8f

__global__ void bce_zero_kernel(float* __restrict__ out) {
    if (threadIdx.x == 0) out[0] = 0.0f;
}

struct RawRow { float4 t4; float l, r; };

__global__ __launch_bounds__(TPB)
void bce_main_kernel(const float* __restrict__ pred,
                     const float* __restrict__ tgt,
                     float* __restrict__ out) {
    const int x4   = threadIdx.x * 4;      // column of this thread's float4
    const int lane = threadIdx.x & 31;
    const bool has_left  = (x4 > 0);
    const bool has_right = (x4 + 4 < Wd);

    const int r0 = blockIdx.x * RPB;       // first global row for this block
    const int y0 = r0 & (Hd - 1);          // row within image (RPB divides Hd)

    const float* tp = tgt  + (size_t)r0 * Wd + x4;
    const float* pp = pred + (size_t)r0 * Wd + x4;

    // raw load: float4 + edge scalars. NO processing here — pure LDG issue.
    auto load_raw = [&](const float* p, RawRow& rr) {
        rr.t4 = *reinterpret_cast<const float4*>(p);
        rr.l = (lane == 0  && has_left ) ? __ldg(p - 1) : 0.0f;
        rr.r = (lane == 31 && has_right) ? __ldg(p + 4) : 0.0f;
    };

    // process a buffered raw row (LDG landed >= 1 iteration ago):
    // horizontal 3-SUM per element (target is exactly 0/1, max == saturating sum).
    // SHUFFLES RUN UNCONDITIONALLY on all lanes (full mask); select afterward.
    auto hsum = [&](const RawRow& rr) -> float4 {
        float4 t = rr.t4;
        float sl = __shfl_up_sync(0xffffffffu, t.w, 1);    // all lanes execute
        float sr = __shfl_down_sync(0xffffffffu, t.x, 1);  // all lanes execute
        float l  = (lane == 0)  ? rr.l : sl;
        float r  = (lane == 31) ? rr.r : sr;
        float4 h;
        h.x = l   + t.x + t.y;
        h.y = t.x + t.y + t.z;
        h.z = t.y + t.z + t.w;
        h.w = t.z + t.w + r;
        return h;
    };

    // ---- prologue ----
    const float4 zero4 = make_float4(0.f, 0.f, 0.f, 0.f);
    float4 hs_m1, hs_0, hs_p1;
    float4 tcur;                 // raw target of row r (loss term)
    RawRow traw;                 // raw target row r+1 (pipeline buffer)

    if (y0 > 0) {
        RawRow t; load_raw(tp - Wd, t);
        hs_m1 = hsum(t);
    } else hs_m1 = zero4;
    {
        RawRow t; load_raw(tp, t);
        hs_0 = hsum(t);
        tcur = t.t4;
    }
    load_raw(tp + Wd, traw);     // row r0+1 always exists (y0 <= Hd-RPB)
    float4 p4 = *reinterpret_cast<const float4*>(pp);

    float acc = 0.0f;

    #pragma unroll
    for (int i = 0; i < RPB; ++i) {
        const int y = y0 + i;

        // ---- issue loads consumed NEXT iteration (fire-and-forget) ----
        RawRow tnew;
        if (y < Hd - 2) {
            load_raw(tp + 2 * Wd, tnew);
        } else {
            tnew.t4 = zero4; tnew.l = 0.f; tnew.r = 0.f;
        }
        float4 p4n;
        if (i < RPB - 1)
            p4n = *reinterpret_cast<const float4*>(pp + Wd);

        // ---- process buffered row r+1 (its LDG landed an iteration ago) ----
        hs_p1 = hsum(traw);

        // ---- loss for row r: all FADD/FMA-pipe algebra ----
        {
            float vs[4] = { hs_m1.x + hs_0.x + hs_p1.x,
                            hs_m1.y + hs_0.y + hs_p1.y,
                            hs_m1.z + hs_0.z + hs_p1.z,
                            hs_m1.w + hs_0.w + hs_p1.w };
            float tv[4] = { tcur.x, tcur.y, tcur.z, tcur.w };
            float xv[4] = { p4.x,   p4.y,   p4.z,   p4.w };
            #pragma unroll
            for (int j = 0; j < 4; ++j) {
                float x = xv[j];
                float t = tv[j];                      // exactly 0.0 or 1.0
                float d = fminf(vs[j], 1.0f);         // dilation indicator
                // w = 1 + 4*d + 15*t   (t=1 -> d=1 -> 20; d=1 -> 5; else 1)
                float w = fmaf(15.0f, t, fmaf(4.0f, d, 1.0f));
                float a  = fabsf(x);
                float sp = __logf(1.0f + __expf(-a)); // log1p(exp(-|x|))
                float base = fmaf(-x, t, fmaxf(x, 0.0f) + sp);
                acc = fmaf(w, base, acc);
            }
        }

        // ---- roll pipeline ----
        hs_m1 = hs_0; hs_0 = hs_p1;
        tcur  = traw.t4;
        traw  = tnew;
        if (i < RPB - 1) p4 = p4n;
        tp += Wd; pp += Wd;
    }

    // ---- block reduction (fixed tree order), then one relaxed atomic ----
    #pragma unroll
    for (int off = 16; off > 0; off >>= 1)
        acc += __shfl_down_sync(0xffffffffu, acc, off);

    __shared__ float smem[TPB / 32];
    const int wid = threadIdx.x >> 5;
    if (lane == 0) smem[wid] = acc;
    __syncthreads();
    if (threadIdx.x == 0) {
        acc = smem[0];
        #pragma unroll
        for (int k = 1; k < TPB / 32; ++k) acc += smem[k];
        // exact 2^-24 scale; relaxed fp32 atomic (REDG) — no fence, no acquire
        atomicAdd(out, acc * INV_N);
    }
}

extern "C" void kernel_launch(void* const* d_in, const int* in_sizes, int n_in,
                              void* d_out, int out_size) {
    const float* pred = (const float*)d_in[0];
    const float* tgt  = (const float*)d_in[1];
    float* out = (float*)d_out;

    bce_zero_kernel<<<1, 32>>>(out);
    bce_main_kernel<<<NBLK, TPB>>>(pred, tgt, out);
}

// round 17
// speedup vs baseline: 1.3017x; 1.3017x over previous
#include <cuda_runtime.h>

#define Wd   1024
#define Hd   1024
#define RPB  8
#define NBLK 2048                 // single strip per block
#define TPB  256                  // 256 threads * 4 floats = 1024 = one row

// 1 / (16 * 1024 * 1024) = 2^-24, exact power of two -> exact scaling
#define INV_N 5.9604644775390625e-8f

struct RawRow { float4 t4; float l, r; };

__device__ __forceinline__ unsigned bits4(float4 t) {
    unsigned m = 0u;
    if (t.x > 0.5f) m |= 1u;
    if (t.y > 0.5f) m |= 2u;
    if (t.z > 0.5f) m |= 4u;
    if (t.w > 0.5f) m |= 8u;
    return m;
}

__global__ __launch_bounds__(TPB)
void bce_main_kernel(const float* __restrict__ pred,
                     const float* __restrict__ tgt,
                     float* __restrict__ out) {
    const int x4   = threadIdx.x * 4;      // column of this thread's float4
    const int lane = threadIdx.x & 31;
    const bool has_left  = (x4 > 0);
    const bool has_right = (x4 + 4 < Wd);

    const int r0 = blockIdx.x * RPB;       // first global row for this block
    const int y0 = r0 & (Hd - 1);          // row within image (RPB divides Hd)

    const float* tp = tgt  + (size_t)r0 * Wd + x4;
    const float* pp = pred + (size_t)r0 * Wd + x4;

    // raw target load: float4 + edge scalars. Pure LDG issue, no processing.
    auto load_raw = [&](const float* p, RawRow& rr) {
        rr.t4 = *reinterpret_cast<const float4*>(p);
        rr.l = (lane == 0  && has_left ) ? __ldg(p - 1) : 0.0f;
        rr.r = (lane == 31 && has_right) ? __ldg(p + 4) : 0.0f;
    };

    // pred load: read-once -> streaming (evict-first), keeps L2 for tgt halos
    auto load_pred = [&](const float* p) -> float4 {
        return __ldcs(reinterpret_cast<const float4*>(p));
    };

    // process a buffered raw row (LDG landed >= 1 iteration ago):
    // occupancy mask m (out) + horizontal 3-max mask (return).
    // Shuffles run unconditionally on all lanes; select afterward.
    auto process = [&](const RawRow& rr, unsigned& m) -> unsigned {
        m = bits4(rr.t4);
        unsigned ml = __shfl_up_sync(0xffffffffu, m, 1);
        unsigned mr = __shfl_down_sync(0xffffffffu, m, 1);
        unsigned l = (lane == 0)  ? (rr.l > 0.5f ? 1u : 0u) : ((ml >> 3) & 1u);
        unsigned r = (lane == 31) ? (rr.r > 0.5f ? 8u : 0u) : ((mr & 1u) << 3);
        return (m | (m << 1) | (m >> 1) | l | r) & 0xFu;
    };

    // ---- prologue ----
    unsigned hm1, h0, hp1, m, m1, dummy;
    RawRow traw;                      // raw tgt row r+1 (pipeline buffer)

    if (y0 > 0) {
        RawRow t; load_raw(tp - Wd, t);
        hm1 = process(t, dummy);
    } else hm1 = 0u;
    {
        RawRow t; load_raw(tp, t);
        h0 = process(t, m);
    }
    load_raw(tp + Wd, traw);          // row r0+1 always exists (y0 <= Hd-RPB)

    // pred pipeline: depth 2 (rows r0 and r0+1 in flight before the loop)
    float4 p4  = load_pred(pp);
    float4 p4n = load_pred(pp + Wd);
    float4 p4nn;

    float acc = 0.0f;

    #pragma unroll
    for (int i = 0; i < RPB; ++i) {
        const int y = y0 + i;

        // ---- issue loads consumed in LATER iterations (fire-and-forget) ----
        RawRow tnew;
        if (y < Hd - 2) {
            load_raw(tp + 2 * Wd, tnew);
        } else {
            tnew.t4 = make_float4(0.f, 0.f, 0.f, 0.f);
            tnew.l = 0.f; tnew.r = 0.f;
        }
        if (i < RPB - 2)
            p4nn = load_pred(pp + 2 * Wd);   // pred row r+2, used in 2 iters

        // ---- process buffered row r+1 (its LDG landed an iteration ago) ----
        hp1 = process(traw, m1);

        const unsigned dil = hm1 | h0 | hp1;   // vertical max = bit OR

        // ---- loss for row r ----
        {
            float xs[4] = {p4.x, p4.y, p4.z, p4.w};
            #pragma unroll
            for (int j = 0; j < 4; ++j) {
                float x = xs[j];
                bool tb = (m   >> j) & 1u;
                bool db = (dil >> j) & 1u;
                float w = tb ? 20.0f : (db ? 5.0f : 1.0f);
                float a  = fabsf(x);
                float sp = __logf(1.0f + __expf(-a));   // log1p(exp(-|x|))
                float base = fmaxf(x, 0.0f) - (tb ? x : 0.0f) + sp;
                acc = fmaf(w, base, acc);
            }
        }

        // ---- roll pipeline ----
        hm1 = h0; h0 = hp1; m = m1;
        traw = tnew;
        p4 = p4n; p4n = p4nn;
        tp += Wd; pp += Wd;
    }

    // ---- block reduction (fixed tree order), then one relaxed atomic ----
    #pragma unroll
    for (int off = 16; off > 0; off >>= 1)
        acc += __shfl_down_sync(0xffffffffu, acc, off);

    __shared__ float smem[TPB / 32];
    const int wid = threadIdx.x >> 5;
    if (lane == 0) smem[wid] = acc;
    __syncthreads();
    if (threadIdx.x == 0) {
        acc = smem[0];
        #pragma unroll
        for (int k = 1; k < TPB / 32; ++k) acc += smem[k];
        // exact 2^-24 scale; relaxed fp32 atomic (REDG) — no fence, no acquire
        atomicAdd(out, acc * INV_N);
    }
}

extern "C" void kernel_launch(void* const* d_in, const int* in_sizes, int n_in,
                              void* d_out, int out_size) {
    const float* pred = (const float*)d_in[0];
    const float* tgt  = (const float*)d_in[1];
    float* out = (float*)d_out;

    // graph memset node: zero the 4-byte output (0x00000000 == 0.0f)
    cudaMemsetAsync(out, 0, sizeof(float));
    bce_main_kernel<<<NBLK, TPB>>>(pred, tgt, out);
}